// round 11
// baseline (speedup 1.0000x reference)
#include <cuda_runtime.h>
#include <cuda_fp16.h>
#include <cstdint>
#include <cfloat>

// ---------------- problem constants ----------------
#define BATCH     32
#define NSPATIAL  4096
#define CDIM      512
#define EDIM      128

#define TM        128                  // rows per CTA tile (M)
#define NCHUNK    (NSPATIAL / TM)      // 32 chunks per batch
#define KS        64                   // K per stage
#define NST       (CDIM / KS)          // 8 stages

// B: full W^T resident in smem: 128 rows(E) x (512 fp16 + 8 pad) = 1040 B/row
#define BSTRIDE   1040
#define B_BYTES   (EDIM * BSTRIDE)     // 133120
// A: per-warp strip 16 rows x 64 k fp16, padded stride 72 (144B), double buf
#define ASTR      72
#define ASTRIP    (16 * ASTR * 2)      // 2304 B
#define A_BYTES   (16 * 2 * ASTRIP)    // 73728
#define SMEM_DYN  (B_BYTES + A_BYTES)  // 206848 B (~202KB)

// scratch: per (batch, chunk, e): top3 + min3 (6 floats) -> 3 MB
__device__ float g_cand[BATCH * NCHUNK * EDIM * 6];
// pre-converted W^T in fp16, plain [E=128][C=512] K-major
__device__ __align__(16) __half g_Wh[EDIM * CDIM];

// ---------------- helpers ----------------
__device__ __forceinline__ uint32_t smem_u32(const void* p) {
    uint32_t a;
    asm("{ .reg .u64 t; cvta.to.shared.u64 t, %1; cvt.u32.u64 %0, t; }"
        : "=r"(a) : "l"(p));
    return a;
}
__device__ __forceinline__ void ldx4(uint32_t* r, uint32_t addr) {
    asm volatile("ldmatrix.sync.aligned.m8n8.x4.shared.b16 {%0,%1,%2,%3}, [%4];"
                 : "=r"(r[0]), "=r"(r[1]), "=r"(r[2]), "=r"(r[3]) : "r"(addr));
}
__device__ __forceinline__ void mma_f16(float* c, const uint32_t* a,
                                        uint32_t b0, uint32_t b1) {
    asm volatile(
        "mma.sync.aligned.m16n8k16.row.col.f32.f16.f16.f32 "
        "{%0,%1,%2,%3}, {%4,%5,%6,%7}, {%8,%9}, {%0,%1,%2,%3};"
        : "+f"(c[0]), "+f"(c[1]), "+f"(c[2]), "+f"(c[3])
        : "r"(a[0]), "r"(a[1]), "r"(a[2]), "r"(a[3]), "r"(b0), "r"(b1));
}
__device__ __forceinline__ void cp16(uint32_t dst, const void* src) {
    asm volatile("cp.async.cg.shared.global [%0], [%1], 16;"
                 :: "r"(dst), "l"(src) : "memory");
}
#define CP_COMMIT() asm volatile("cp.async.commit_group;" ::: "memory")
#define CP_WAIT0()  asm volatile("cp.async.wait_group 0;" ::: "memory")

// fp32 pair -> fp16x2 (single rounding)
__device__ __forceinline__ uint32_t cvt_h2(float x, float y) {
    __half2 h = __floats2half2_rn(x, y);
    return *(uint32_t*)&h;
}

// ---- sorted top-3 / min-3 insertion ----
__device__ __forceinline__ void ins_top(float v, float& t0, float& t1, float& t2) {
    if (v > t2) { if (v > t1) { t2 = t1; if (v > t0) { t1 = t0; t0 = v; } else t1 = v; } else t2 = v; }
}
__device__ __forceinline__ void ins_min(float v, float& m0, float& m1, float& m2) {
    if (v < m2) { if (v < m1) { m2 = m1; if (v < m0) { m1 = m0; m0 = v; } else m1 = v; } else m2 = v; }
}

// ================= kernel 0: W^T -> fp16 =================
__global__ void weldon_prepw_kernel(const float* __restrict__ W) {
    int idx = blockIdx.x * 512 + threadIdx.x;   // 0..32767
    int e = idx >> 8;                           // 0..127
    int k = (idx & 255) * 2;                    // 0..510 step 2
    float w0 = W[(size_t)k * EDIM + e];
    float w1 = W[(size_t)(k + 1) * EDIM + e];
    *(uint32_t*)&g_Wh[(size_t)e * CDIM + k] = cvt_h2(w0, w1);
}

// ================= kernel 1: barrier-free HMMA GEMM + pooling =================
// grid = (NCHUNK, BATCH), 512 threads, 16 warps:
//   warp tile 16(M) x 64(N): wm = wid&7 exclusive strip, wn = wid>>3
//   B: full W^T in smem (loaded once); A: per-warp private strip (syncwarp only)
__global__ __launch_bounds__(512, 1)
void weldon_gemm_pool_kernel(const float* __restrict__ x) {
    extern __shared__ char sm[];
    const uint32_t sb = smem_u32(sm);

    __shared__ float cand_s[8][EDIM][6];        // 24KB static

    const int tid = threadIdx.x;
    const int lane = tid & 31;
    const int wid = tid >> 5;
    const int wm = wid & 7;                     // 8 M-strips of 16
    const int wn = wid >> 3;                    // 2 N-halves of 64
    const int chunk = blockIdx.x;
    const int b = blockIdx.y;

    const float* xg = x + ((size_t)b * NSPATIAL + (size_t)chunk * TM) * CDIM;
    const float* ag = xg + (size_t)(wm * 16) * CDIM;   // warp's 16 rows

    // A strip base (bytes) for this warp
    const uint32_t astrip = sb + B_BYTES + wid * 2 * ASTRIP;
    const int arow = lane >> 4;                 // 0/1
    const int acol = (lane & 15) * 4;           // 0..60

    // A ldmatrix per-lane offset within strip
    const int aoff = (lane & 15) * (ASTR * 2) + (lane >> 4) * 16;
    // B ldmatrix per-lane offsets (4 tiles of 16 rows over 64 N-rows)
    int boff[4];
#pragma unroll
    for (int p = 0; p < 4; ++p)
        boff[p] = (wn * 64 + p * 16 + (lane & 7) + ((lane >> 4) & 1) * 8) * BSTRIDE +
                  ((lane >> 3) & 1) * 16;

    float acc[8][4];
#pragma unroll
    for (int nt = 0; nt < 8; ++nt)
#pragma unroll
        for (int j = 0; j < 4; ++j) acc[nt][j] = 0.f;

    float4 pf[8];
    auto ldgA = [&](int s) {
#pragma unroll
        for (int u = 0; u < 8; ++u)
            pf[u] = *(const float4*)(ag + (size_t)(u * 2 + arow) * CDIM + s * KS + acol);
    };
    auto cvtA = [&](int buf) {
        const uint32_t base = astrip + buf * ASTRIP;
#pragma unroll
        for (int u = 0; u < 8; ++u) {
            uint2 hv = make_uint2(cvt_h2(pf[u].x, pf[u].y), cvt_h2(pf[u].z, pf[u].w));
            *(uint2*)((char*)sm + (base - sb) + (u * 2 + arow) * (ASTR * 2) + acol * 2) = hv;
        }
    };

    // ---- prologue: B full load (once) + A stage 0/1 ----
    {
        // 128 rows x 64 16B-chunks = 8192 chunks; 16 per thread
#pragma unroll
        for (int u = 0; u < 16; ++u) {
            int idx = tid + u * 512;
            int row = idx >> 6, c = idx & 63;
            cp16(sb + row * BSTRIDE + c * 16,
                 (const char*)g_Wh + (size_t)row * (CDIM * 2) + c * 16);
        }
        CP_COMMIT();
        ldgA(0);
        cvtA(0);
        ldgA(1);
        CP_WAIT0();
        __syncthreads();    // B visible to all warps; only barrier before epilogue
    }

    // ---- main stage loop: NO block barriers ----
#pragma unroll
    for (int s = 0; s < NST; ++s) {
        __syncwarp();       // own strip: STS (prev cvt) -> LDSM ordering
        const uint32_t abase = astrip + (s & 1) * ASTRIP;
        const int kbase = s * 128;              // byte offset of stage in B rows
#pragma unroll
        for (int k16 = 0; k16 < 4; ++k16) {
            const int kbyte = k16 * 32;
            uint32_t a_r[4], b_r[4][4];
            ldx4(a_r, abase + aoff + kbyte);
#pragma unroll
            for (int p = 0; p < 4; ++p)
                ldx4(b_r[p], sb + boff[p] + kbase + kbyte);
#pragma unroll
            for (int nt = 0; nt < 8; ++nt)
                mma_f16(acc[nt], a_r,
                        b_r[nt >> 1][(nt & 1) * 2], b_r[nt >> 1][(nt & 1) * 2 + 1]);
        }
        if (s + 1 < NST) cvtA((s + 1) & 1);     // pf holds stage s+1
        if (s + 2 < NST) ldgA(s + 2);
    }

    // ---- epilogue: register-level per-column top3/min3 via shuffles ----
    // thread holds rows wm*16+gid, +8; cols wn*64 + nt*8 + tig*2 + h
#pragma unroll
    for (int ci = 0; ci < 16; ++ci) {
        const int nt = ci >> 1, h = ci & 1;
        float v0 = acc[nt][h], v1 = acc[nt][h + 2];
        float t0 = fmaxf(v0, v1), t1 = fminf(v0, v1), t2 = -FLT_MAX;
        float m0 = fminf(v0, v1), m1 = fmaxf(v0, v1), m2 = FLT_MAX;
#pragma unroll
        for (int msk = 4; msk <= 16; msk <<= 1) {
            float o0 = __shfl_xor_sync(0xffffffffu, t0, msk);
            float o1 = __shfl_xor_sync(0xffffffffu, t1, msk);
            float o2 = __shfl_xor_sync(0xffffffffu, t2, msk);
            ins_top(o0, t0, t1, t2); ins_top(o1, t0, t1, t2); ins_top(o2, t0, t1, t2);
            float p0 = __shfl_xor_sync(0xffffffffu, m0, msk);
            float p1 = __shfl_xor_sync(0xffffffffu, m1, msk);
            float p2 = __shfl_xor_sync(0xffffffffu, m2, msk);
            ins_min(p0, m0, m1, m2); ins_min(p1, m0, m1, m2); ins_min(p2, m0, m1, m2);
        }
        if (lane < 4) {
            int col = wn * 64 + nt * 8 + lane * 2 + h;
            cand_s[wm][col][0] = t0; cand_s[wm][col][1] = t1; cand_s[wm][col][2] = t2;
            cand_s[wm][col][3] = m0; cand_s[wm][col][4] = m1; cand_s[wm][col][5] = m2;
        }
    }
    __syncthreads();

    if (tid < EDIM) {
        float t0 = -FLT_MAX, t1 = -FLT_MAX, t2 = -FLT_MAX;
        float m0 = FLT_MAX, m1 = FLT_MAX, m2 = FLT_MAX;
#pragma unroll
        for (int s2 = 0; s2 < 8; ++s2) {
            ins_top(cand_s[s2][tid][0], t0, t1, t2);
            ins_top(cand_s[s2][tid][1], t0, t1, t2);
            ins_top(cand_s[s2][tid][2], t0, t1, t2);
            ins_min(cand_s[s2][tid][3], m0, m1, m2);
            ins_min(cand_s[s2][tid][4], m0, m1, m2);
            ins_min(cand_s[s2][tid][5], m0, m1, m2);
        }
        float* dst = g_cand + ((size_t)(b * NCHUNK + chunk) * EDIM + tid) * 6;
        dst[0] = t0; dst[1] = t1; dst[2] = t2;
        dst[3] = m0; dst[4] = m1; dst[5] = m2;
    }
}

// ================= kernel 2: merge + pool + L2 normalize =================
// grid = BATCH, block = (128, 8)
__global__ void weldon_reduce_kernel(float* __restrict__ out) {
    const int b = blockIdx.x;
    const int e = threadIdx.x;
    const int sub = threadIdx.y;

    __shared__ float cand_s[8][EDIM][6];
    __shared__ float ps_s[EDIM];
    __shared__ float wsum[4];

    float t0 = -FLT_MAX, t1 = -FLT_MAX, t2 = -FLT_MAX;
    float m0 = FLT_MAX, m1 = FLT_MAX, m2 = FLT_MAX;
    const float* bb = g_cand + (size_t)b * NCHUNK * EDIM * 6 + (size_t)e * 6;
#pragma unroll
    for (int c = sub; c < NCHUNK; c += 8) {
        const float* p = bb + (size_t)c * EDIM * 6;
        ins_top(p[0], t0, t1, t2);
        ins_top(p[1], t0, t1, t2);
        ins_top(p[2], t0, t1, t2);
        ins_min(p[3], m0, m1, m2);
        ins_min(p[4], m0, m1, m2);
        ins_min(p[5], m0, m1, m2);
    }
    cand_s[sub][e][0] = t0; cand_s[sub][e][1] = t1; cand_s[sub][e][2] = t2;
    cand_s[sub][e][3] = m0; cand_s[sub][e][4] = m1; cand_s[sub][e][5] = m2;
    __syncthreads();

    if (sub == 0) {
        for (int s2 = 1; s2 < 8; ++s2) {
            ins_top(cand_s[s2][e][0], t0, t1, t2);
            ins_top(cand_s[s2][e][1], t0, t1, t2);
            ins_top(cand_s[s2][e][2], t0, t1, t2);
            ins_min(cand_s[s2][e][3], m0, m1, m2);
            ins_min(cand_s[s2][e][4], m0, m1, m2);
            ins_min(cand_s[s2][e][5], m0, m1, m2);
        }
        float ps = (t0 + t1 + t2) + (m0 + m1 + m2);
        ps_s[e] = ps;
        float sq = ps * ps;
#pragma unroll
        for (int off = 16; off > 0; off >>= 1)
            sq += __shfl_xor_sync(0xffffffffu, sq, off);
        if ((e & 31) == 0) wsum[e >> 5] = sq;
    }
    __syncthreads();
    if (sub == 0) {
        float tot = wsum[0] + wsum[1] + wsum[2] + wsum[3];
        out[b * EDIM + e] = ps_s[e] * rsqrtf(fmaxf(tot, 1e-12f));
    }
}

extern "C" void kernel_launch(void* const* d_in, const int* in_sizes, int n_in,
                              void* d_out, int out_size) {
    const float* x = (const float*)d_in[0];   // [32, 64, 64, 512] fp32
    const float* W = (const float*)d_in[1];   // [512, 128] fp32
    float* out = (float*)d_out;               // [32, 128] fp32
    (void)in_sizes; (void)n_in; (void)out_size;

    cudaFuncSetAttribute(weldon_gemm_pool_kernel,
                         cudaFuncAttributeMaxDynamicSharedMemorySize, SMEM_DYN);

    weldon_prepw_kernel<<<64, 512>>>(W);
    weldon_gemm_pool_kernel<<<dim3(NCHUNK, BATCH), 512, SMEM_DYN>>>(x);
    weldon_reduce_kernel<<<BATCH, dim3(EDIM, 8)>>>(out);
}

// round 12
// speedup vs baseline: 1.3971x; 1.3971x over previous
#include <cuda_runtime.h>
#include <cuda_fp16.h>
#include <cstdint>
#include <cfloat>

// ---------------- problem constants ----------------
#define BATCH     32
#define NSPATIAL  4096
#define CDIM      512
#define EDIM      128

#define TM        256                  // rows per CTA tile (M)
#define NCHUNK    (NSPATIAL / TM)      // 16 chunks per batch
#define KS        64                   // K per stage
#define NST       (CDIM / KS)          // 8 stages
#define ASTR      72                   // padded row stride (fp16 elems) = 144B
#define ATILEB    (TM * ASTR * 2)      // 36864 B per A buffer
#define BTILEB    (EDIM * ASTR * 2)    // 18432 B per B buffer
#define SMEM_DYN  (2 * ATILEB + 2 * BTILEB)   // 110.6KB

// scratch: per (batch, chunk, e): top3 + min3 (6 floats) -> 1.5 MB
__device__ float g_cand[BATCH * NCHUNK * EDIM * 6];
// pre-converted W^T in fp16, plain [E=128][C=512] K-major
__device__ __align__(16) __half g_Wh[EDIM * CDIM];

// ---------------- helpers ----------------
__device__ __forceinline__ uint32_t smem_u32(const void* p) {
    uint32_t a;
    asm("{ .reg .u64 t; cvta.to.shared.u64 t, %1; cvt.u32.u64 %0, t; }"
        : "=r"(a) : "l"(p));
    return a;
}
__device__ __forceinline__ void ldx4(uint32_t* r, uint32_t addr) {
    asm volatile("ldmatrix.sync.aligned.m8n8.x4.shared.b16 {%0,%1,%2,%3}, [%4];"
                 : "=r"(r[0]), "=r"(r[1]), "=r"(r[2]), "=r"(r[3]) : "r"(addr));
}
__device__ __forceinline__ void mma_f16(float* c, const uint32_t* a,
                                        uint32_t b0, uint32_t b1) {
    asm volatile(
        "mma.sync.aligned.m16n8k16.row.col.f32.f16.f16.f32 "
        "{%0,%1,%2,%3}, {%4,%5,%6,%7}, {%8,%9}, {%0,%1,%2,%3};"
        : "+f"(c[0]), "+f"(c[1]), "+f"(c[2]), "+f"(c[3])
        : "r"(a[0]), "r"(a[1]), "r"(a[2]), "r"(a[3]), "r"(b0), "r"(b1));
}
__device__ __forceinline__ void cp16(uint32_t dst, const void* src) {
    asm volatile("cp.async.cg.shared.global [%0], [%1], 16;"
                 :: "r"(dst), "l"(src) : "memory");
}
#define CP_COMMIT() asm volatile("cp.async.commit_group;" ::: "memory")
#define CP_WAIT0()  asm volatile("cp.async.wait_group 0;" ::: "memory")

// fp32 pair -> fp16x2 (single rounding)
__device__ __forceinline__ uint32_t cvt_h2(float x, float y) {
    __half2 h = __floats2half2_rn(x, y);
    return *(uint32_t*)&h;
}

// ---- sorted top-3 / min-3 insertion ----
__device__ __forceinline__ void ins_top(float v, float& t0, float& t1, float& t2) {
    if (v > t2) { if (v > t1) { t2 = t1; if (v > t0) { t1 = t0; t0 = v; } else t1 = v; } else t2 = v; }
}
__device__ __forceinline__ void ins_min(float v, float& m0, float& m1, float& m2) {
    if (v < m2) { if (v < m1) { m2 = m1; if (v < m0) { m1 = m0; m0 = v; } else m1 = v; } else m2 = v; }
}

// ================= kernel 0: W^T -> fp16 =================
__global__ void weldon_prepw_kernel(const float* __restrict__ W) {
    int idx = blockIdx.x * 512 + threadIdx.x;   // 0..32767
    int e = idx >> 8;                           // 0..127
    int k = (idx & 255) * 2;                    // 0..510 step 2
    float w0 = W[(size_t)k * EDIM + e];
    float w1 = W[(size_t)(k + 1) * EDIM + e];
    *(uint32_t*)&g_Wh[(size_t)e * CDIM + k] = cvt_h2(w0, w1);
}

// ================= kernel 1: HMMA GEMM + register pooling =================
// grid = (NCHUNK, BATCH) = 512 CTAs, 512 threads (16 warps, 64x32 warp tiles)
__global__ __launch_bounds__(512, 1)
void weldon_gemm_pool_kernel(const float* __restrict__ x) {
    extern __shared__ char sm[];
    const uint32_t sb = smem_u32(sm);

    __shared__ float cand_s[4][EDIM][6];        // 12KB static

    const int tid = threadIdx.x;
    const int lane = tid & 31;
    const int wid = tid >> 5;
    const int wm = wid & 3;                     // 4 M-groups of 64
    const int wn = wid >> 2;                    // 4 N-groups of 32
    const int chunk = blockIdx.x;
    const int b = blockIdx.y;

    const float* xg = x + ((size_t)b * NSPATIAL + (size_t)chunk * TM) * CDIM;

    // buffer byte offsets: A (2 bufs), B (2 bufs)
    auto OFF_A = [](int buf) { return buf * ATILEB; };
    auto OFF_B = [](int buf) { return 2 * ATILEB + buf * BTILEB; };

    // ldmatrix per-lane address offsets (bytes within a tile)
    int aoff[4], boff[2];
#pragma unroll
    for (int mt = 0; mt < 4; ++mt)
        aoff[mt] = ((wm * 64 + mt * 16 + (lane & 15)) * ASTR + (lane >> 4) * 8) * 2;
#pragma unroll
    for (int p = 0; p < 2; ++p)
        boff[p] = ((wn * 32 + p * 16 + (lane & 7) + (lane >> 4) * 8) * ASTR +
                   ((lane >> 3) & 1) * 8) * 2;

    float acc[4][4][4];
#pragma unroll
    for (int mt = 0; mt < 4; ++mt)
#pragma unroll
        for (int nt = 0; nt < 4; ++nt)
#pragma unroll
            for (int j = 0; j < 4; ++j) acc[mt][nt][j] = 0.f;

    // ---- prologue: stage 0 ----
    {
#pragma unroll
        for (int u = 0; u < 8; ++u) {
            int idx = tid + u * 512;            // 0..4095 float4s (256 rows x 16)
            int row = idx >> 4, kq = (idx & 15) * 4;
            float4 f = *(const float4*)(xg + (size_t)row * CDIM + kq);
            uint2 hv = make_uint2(cvt_h2(f.x, f.y), cvt_h2(f.z, f.w));
            *(uint2*)(sm + OFF_A(0) + row * (ASTR * 2) + kq * 2) = hv;
        }
#pragma unroll
        for (int u = 0; u < 2; ++u) {
            int idx = tid + u * 512;            // 0..1023 16B chunks
            int row = idx >> 3, ck = (idx & 7) * 8;
            int doff = row * (ASTR * 2) + ck * 2;
            cp16(sb + OFF_B(0) + doff, (const char*)g_Wh + ((size_t)row * CDIM + ck) * 2);
        }
        CP_COMMIT();
        CP_WAIT0();
        __syncthreads();
    }

    // ---- main stage loop ----
#pragma unroll
    for (int s = 0; s < NST; ++s) {
        const int buf = s & 1;
        const int nb = buf ^ 1;
        float4 pf[8];
        if (s + 1 < NST) {
            const int kb = (s + 1) * KS;
#pragma unroll
            for (int u = 0; u < 8; ++u) {
                int idx = tid + u * 512;
                int row = idx >> 4, kq = (idx & 15) * 4;
                pf[u] = *(const float4*)(xg + (size_t)row * CDIM + kb + kq);
            }
#pragma unroll
            for (int u = 0; u < 2; ++u) {
                int idx = tid + u * 512;
                int row = idx >> 3, ck = (idx & 7) * 8;
                int doff = row * (ASTR * 2) + ck * 2;
                cp16(sb + OFF_B(nb) + doff,
                     (const char*)g_Wh + ((size_t)row * CDIM + kb + ck) * 2);
            }
            CP_COMMIT();
        }

        // ---- MMA over current buffer: 4 k16 steps ----
#pragma unroll
        for (int k16 = 0; k16 < 4; ++k16) {
            const int kbyte = k16 * 32;
            uint32_t a_r[4][4], b_r[2][4];
#pragma unroll
            for (int mt = 0; mt < 4; ++mt)
                ldx4(a_r[mt], sb + OFF_A(buf) + aoff[mt] + kbyte);
#pragma unroll
            for (int p = 0; p < 2; ++p)
                ldx4(b_r[p], sb + OFF_B(buf) + boff[p] + kbyte);
#pragma unroll
            for (int mt = 0; mt < 4; ++mt)
#pragma unroll
                for (int nt = 0; nt < 4; ++nt) {
                    uint32_t b0 = b_r[nt >> 1][(nt & 1) * 2];
                    uint32_t b1 = b_r[nt >> 1][(nt & 1) * 2 + 1];
                    mma_f16(acc[mt][nt], a_r[mt], b0, b1);
                }
        }

        if (s + 1 < NST) {
#pragma unroll
            for (int u = 0; u < 8; ++u) {
                int idx = tid + u * 512;
                int row = idx >> 4, kq = (idx & 15) * 4;
                uint2 hv = make_uint2(cvt_h2(pf[u].x, pf[u].y), cvt_h2(pf[u].z, pf[u].w));
                *(uint2*)(sm + OFF_A(nb) + row * (ASTR * 2) + kq * 2) = hv;
            }
            CP_WAIT0();
        }
        __syncthreads();
    }

    // ---- epilogue: register-level per-column top3/min3 via shuffles ----
    // thread holds rows wm*64 + mt*16 + gid, +8 (mt 0..3); cols wn*32+nt*8+tig*2+h
#pragma unroll
    for (int ci = 0; ci < 8; ++ci) {
        const int nt = ci >> 1, h = ci & 1;
        float t0 = -FLT_MAX, t1 = -FLT_MAX, t2 = -FLT_MAX;
        float m0 = FLT_MAX, m1 = FLT_MAX, m2 = FLT_MAX;
#pragma unroll
        for (int mt = 0; mt < 4; ++mt) {
            float v0 = acc[mt][nt][h];
            float v1 = acc[mt][nt][h + 2];
            ins_top(v0, t0, t1, t2); ins_min(v0, m0, m1, m2);
            ins_top(v1, t0, t1, t2); ins_min(v1, m0, m1, m2);
        }
        // reduce across gid lanes (bits 2..4 of lane id) -> 64 rows of wm group
#pragma unroll
        for (int msk = 4; msk <= 16; msk <<= 1) {
            float o0 = __shfl_xor_sync(0xffffffffu, t0, msk);
            float o1 = __shfl_xor_sync(0xffffffffu, t1, msk);
            float o2 = __shfl_xor_sync(0xffffffffu, t2, msk);
            ins_top(o0, t0, t1, t2); ins_top(o1, t0, t1, t2); ins_top(o2, t0, t1, t2);
            float p0 = __shfl_xor_sync(0xffffffffu, m0, msk);
            float p1 = __shfl_xor_sync(0xffffffffu, m1, msk);
            float p2 = __shfl_xor_sync(0xffffffffu, m2, msk);
            ins_min(p0, m0, m1, m2); ins_min(p1, m0, m1, m2); ins_min(p2, m0, m1, m2);
        }
        if (lane < 4) {
            int col = wn * 32 + nt * 8 + lane * 2 + h;
            cand_s[wm][col][0] = t0; cand_s[wm][col][1] = t1; cand_s[wm][col][2] = t2;
            cand_s[wm][col][3] = m0; cand_s[wm][col][4] = m1; cand_s[wm][col][5] = m2;
        }
    }
    __syncthreads();

    if (tid < EDIM) {
        float t0 = -FLT_MAX, t1 = -FLT_MAX, t2 = -FLT_MAX;
        float m0 = FLT_MAX, m1 = FLT_MAX, m2 = FLT_MAX;
#pragma unroll
        for (int s2 = 0; s2 < 4; ++s2) {
            ins_top(cand_s[s2][tid][0], t0, t1, t2);
            ins_top(cand_s[s2][tid][1], t0, t1, t2);
            ins_top(cand_s[s2][tid][2], t0, t1, t2);
            ins_min(cand_s[s2][tid][3], m0, m1, m2);
            ins_min(cand_s[s2][tid][4], m0, m1, m2);
            ins_min(cand_s[s2][tid][5], m0, m1, m2);
        }
        float* dst = g_cand + ((size_t)(b * NCHUNK + chunk) * EDIM + tid) * 6;
        dst[0] = t0; dst[1] = t1; dst[2] = t2;
        dst[3] = m0; dst[4] = m1; dst[5] = m2;
    }
}

// ================= kernel 2: merge + pool + L2 normalize =================
// grid = BATCH, block = (128, 8)
__global__ void weldon_reduce_kernel(float* __restrict__ out) {
    const int b = blockIdx.x;
    const int e = threadIdx.x;
    const int sub = threadIdx.y;

    __shared__ float cand_s[8][EDIM][6];
    __shared__ float ps_s[EDIM];
    __shared__ float wsum[4];

    float t0 = -FLT_MAX, t1 = -FLT_MAX, t2 = -FLT_MAX;
    float m0 = FLT_MAX, m1 = FLT_MAX, m2 = FLT_MAX;
    const float* bb = g_cand + (size_t)b * NCHUNK * EDIM * 6 + (size_t)e * 6;
#pragma unroll
    for (int c = sub; c < NCHUNK; c += 8) {
        const float* p = bb + (size_t)c * EDIM * 6;
        ins_top(p[0], t0, t1, t2);
        ins_top(p[1], t0, t1, t2);
        ins_top(p[2], t0, t1, t2);
        ins_min(p[3], m0, m1, m2);
        ins_min(p[4], m0, m1, m2);
        ins_min(p[5], m0, m1, m2);
    }
    cand_s[sub][e][0] = t0; cand_s[sub][e][1] = t1; cand_s[sub][e][2] = t2;
    cand_s[sub][e][3] = m0; cand_s[sub][e][4] = m1; cand_s[sub][e][5] = m2;
    __syncthreads();

    if (sub == 0) {
        for (int s2 = 1; s2 < 8; ++s2) {
            ins_top(cand_s[s2][e][0], t0, t1, t2);
            ins_top(cand_s[s2][e][1], t0, t1, t2);
            ins_top(cand_s[s2][e][2], t0, t1, t2);
            ins_min(cand_s[s2][e][3], m0, m1, m2);
            ins_min(cand_s[s2][e][4], m0, m1, m2);
            ins_min(cand_s[s2][e][5], m0, m1, m2);
        }
        float ps = (t0 + t1 + t2) + (m0 + m1 + m2);
        ps_s[e] = ps;
        float sq = ps * ps;
#pragma unroll
        for (int off = 16; off > 0; off >>= 1)
            sq += __shfl_xor_sync(0xffffffffu, sq, off);
        if ((e & 31) == 0) wsum[e >> 5] = sq;
    }
    __syncthreads();
    if (sub == 0) {
        float tot = wsum[0] + wsum[1] + wsum[2] + wsum[3];
        out[b * EDIM + e] = ps_s[e] * rsqrtf(fmaxf(tot, 1e-12f));
    }
}

extern "C" void kernel_launch(void* const* d_in, const int* in_sizes, int n_in,
                              void* d_out, int out_size) {
    const float* x = (const float*)d_in[0];   // [32, 64, 64, 512] fp32
    const float* W = (const float*)d_in[1];   // [512, 128] fp32
    float* out = (float*)d_out;               // [32, 128] fp32
    (void)in_sizes; (void)n_in; (void)out_size;

    cudaFuncSetAttribute(weldon_gemm_pool_kernel,
                         cudaFuncAttributeMaxDynamicSharedMemorySize, SMEM_DYN);

    weldon_prepw_kernel<<<64, 512>>>(W);
    weldon_gemm_pool_kernel<<<dim3(NCHUNK, BATCH), 512, SMEM_DYN>>>(x);
    weldon_reduce_kernel<<<BATCH, dim3(EDIM, 8)>>>(out);
}

// round 13
// speedup vs baseline: 1.6268x; 1.1644x over previous
#include <cuda_runtime.h>
#include <cuda_fp16.h>
#include <cstdint>
#include <cfloat>

// ---------------- problem constants ----------------
#define BATCH     32
#define NSPATIAL  4096
#define CDIM      512
#define EDIM      128

#define TM        128                  // rows per CTA tile (M)
#define NCHUNK    (NSPATIAL / TM)      // 32 chunks per batch
#define KS        128                  // K per stage
#define NST       (CDIM / KS)          // 4 stages
#define ASTR      136                  // padded row stride (fp16 elems) = 272B (17x16B)
#define TILEB     (TM * ASTR * 2)      // 34816 B per tile buffer
#define SMEM_DYN  (4 * TILEB)          // A0 A1 B0 B1 = 136KB

// scratch: per (batch, chunk, e): top3 + min3 (6 floats) -> 3 MB
__device__ float g_cand[BATCH * NCHUNK * EDIM * 6];
// pre-converted W^T in fp16, plain [E=128][C=512] K-major
__device__ __align__(16) __half g_Wh[EDIM * CDIM];

// ---------------- helpers ----------------
__device__ __forceinline__ uint32_t smem_u32(const void* p) {
    uint32_t a;
    asm("{ .reg .u64 t; cvta.to.shared.u64 t, %1; cvt.u32.u64 %0, t; }"
        : "=r"(a) : "l"(p));
    return a;
}
__device__ __forceinline__ void ldx4(uint32_t* r, uint32_t addr) {
    asm volatile("ldmatrix.sync.aligned.m8n8.x4.shared.b16 {%0,%1,%2,%3}, [%4];"
                 : "=r"(r[0]), "=r"(r[1]), "=r"(r[2]), "=r"(r[3]) : "r"(addr));
}
__device__ __forceinline__ void mma_f16(float* c, const uint32_t* a,
                                        uint32_t b0, uint32_t b1) {
    asm volatile(
        "mma.sync.aligned.m16n8k16.row.col.f32.f16.f16.f32 "
        "{%0,%1,%2,%3}, {%4,%5,%6,%7}, {%8,%9}, {%0,%1,%2,%3};"
        : "+f"(c[0]), "+f"(c[1]), "+f"(c[2]), "+f"(c[3])
        : "r"(a[0]), "r"(a[1]), "r"(a[2]), "r"(a[3]), "r"(b0), "r"(b1));
}
__device__ __forceinline__ void cp16(uint32_t dst, const void* src) {
    asm volatile("cp.async.cg.shared.global [%0], [%1], 16;"
                 :: "r"(dst), "l"(src) : "memory");
}
#define CP_COMMIT() asm volatile("cp.async.commit_group;" ::: "memory")
#define CP_WAIT0()  asm volatile("cp.async.wait_group 0;" ::: "memory")

// fp32 pair -> fp16x2 (single rounding)
__device__ __forceinline__ uint32_t cvt_h2(float x, float y) {
    __half2 h = __floats2half2_rn(x, y);
    return *(uint32_t*)&h;
}

// ---- sorted top-3 / min-3 insertion ----
__device__ __forceinline__ void ins_top(float v, float& t0, float& t1, float& t2) {
    if (v > t2) { if (v > t1) { t2 = t1; if (v > t0) { t1 = t0; t0 = v; } else t1 = v; } else t2 = v; }
}
__device__ __forceinline__ void ins_min(float v, float& m0, float& m1, float& m2) {
    if (v < m2) { if (v < m1) { m2 = m1; if (v < m0) { m1 = m0; m0 = v; } else m1 = v; } else m2 = v; }
}

// ================= kernel 0: W^T -> fp16 =================
__global__ void weldon_prepw_kernel(const float* __restrict__ W) {
    int idx = blockIdx.x * 512 + threadIdx.x;   // 0..32767
    int e = idx >> 8;                           // 0..127
    int k = (idx & 255) * 2;                    // 0..510 step 2
    float w0 = W[(size_t)k * EDIM + e];
    float w1 = W[(size_t)(k + 1) * EDIM + e];
    *(uint32_t*)&g_Wh[(size_t)e * CDIM + k] = cvt_h2(w0, w1);
}

// ================= kernel 1: HMMA GEMM + per-chunk pooling =================
// grid = (NCHUNK, BATCH), 512 threads (16 warps, 32x32 warp tiles), KS=128
__global__ __launch_bounds__(512, 1)
void weldon_gemm_pool_kernel(const float* __restrict__ x) {
    extern __shared__ char sm[];
    const uint32_t sb = smem_u32(sm);
    float* Fs = (float*)sm;                     // 64KB overlay after GEMM

    __shared__ float cand_s[4][EDIM][6];

    const int tid = threadIdx.x;
    const int lane = tid & 31;
    const int wid = tid >> 5;
    const int wm = wid & 3;                     // 4 M-groups of 32
    const int wn = wid >> 2;                    // 4 N-groups of 32
    const int chunk = blockIdx.x;
    const int b = blockIdx.y;

    const float* xg = x + ((size_t)b * NSPATIAL + (size_t)chunk * TM) * CDIM;

    // buffer byte offsets: A (2 bufs), B (2 bufs)
    auto OFF_A = [](int buf) { return buf * TILEB; };
    auto OFF_B = [](int buf) { return (2 + buf) * TILEB; };

    // ldmatrix per-lane address offsets (bytes within a tile)
    int aoff[2], boff[2];
#pragma unroll
    for (int mt = 0; mt < 2; ++mt)
        aoff[mt] = ((wm * 32 + mt * 16 + (lane & 15)) * ASTR + (lane >> 4) * 8) * 2;
#pragma unroll
    for (int p = 0; p < 2; ++p)
        boff[p] = ((wn * 32 + p * 16 + (lane & 7) + (lane >> 4) * 8) * ASTR +
                   ((lane >> 3) & 1) * 8) * 2;

    float acc[2][4][4];
#pragma unroll
    for (int mt = 0; mt < 2; ++mt)
#pragma unroll
        for (int nt = 0; nt < 4; ++nt)
#pragma unroll
            for (int j = 0; j < 4; ++j) acc[mt][nt][j] = 0.f;

    // ---- prologue: stage 0 ----
    {
        // A: 128 rows x 128 k fp32 = 4096 float4s, 8 per thread
#pragma unroll
        for (int u = 0; u < 8; ++u) {
            int idx = tid + u * 512;
            int row = idx >> 5, kq = (idx & 31) * 4;
            float4 f = *(const float4*)(xg + (size_t)row * CDIM + kq);
            uint2 hv = make_uint2(cvt_h2(f.x, f.y), cvt_h2(f.z, f.w));
            *(uint2*)(sm + OFF_A(0) + row * (ASTR * 2) + kq * 2) = hv;
        }
        // B: 128 rows x 256B = 2048 16B chunks, 4 per thread
#pragma unroll
        for (int u = 0; u < 4; ++u) {
            int idx = tid + u * 512;
            int row = idx >> 4, ck = (idx & 15) * 8;
            int doff = row * (ASTR * 2) + ck * 2;
            cp16(sb + OFF_B(0) + doff, (const char*)g_Wh + ((size_t)row * CDIM + ck) * 2);
        }
        CP_COMMIT();
        CP_WAIT0();
        __syncthreads();
    }

    // ---- main stage loop (4 stages) ----
#pragma unroll
    for (int s = 0; s < NST; ++s) {
        const int buf = s & 1;
        const int nb = buf ^ 1;
        float4 pf[8];
        if (s + 1 < NST) {
            const int kb = (s + 1) * KS;
#pragma unroll
            for (int u = 0; u < 8; ++u) {
                int idx = tid + u * 512;
                int row = idx >> 5, kq = (idx & 31) * 4;
                pf[u] = *(const float4*)(xg + (size_t)row * CDIM + kb + kq);
            }
#pragma unroll
            for (int u = 0; u < 4; ++u) {
                int idx = tid + u * 512;
                int row = idx >> 4, ck = (idx & 15) * 8;
                int doff = row * (ASTR * 2) + ck * 2;
                cp16(sb + OFF_B(nb) + doff,
                     (const char*)g_Wh + ((size_t)row * CDIM + kb + ck) * 2);
            }
            CP_COMMIT();
        }

        // ---- MMA over current buffer: 8 k16 steps, 1 product ----
#pragma unroll
        for (int k16 = 0; k16 < 8; ++k16) {
            const int kbyte = k16 * 32;
            uint32_t a_r[2][4], b_r[2][4];
#pragma unroll
            for (int mt = 0; mt < 2; ++mt)
                ldx4(a_r[mt], sb + OFF_A(buf) + aoff[mt] + kbyte);
#pragma unroll
            for (int p = 0; p < 2; ++p)
                ldx4(b_r[p], sb + OFF_B(buf) + boff[p] + kbyte);
#pragma unroll
            for (int mt = 0; mt < 2; ++mt)
#pragma unroll
                for (int nt = 0; nt < 4; ++nt) {
                    uint32_t b0 = b_r[nt >> 1][(nt & 1) * 2];
                    uint32_t b1 = b_r[nt >> 1][(nt & 1) * 2 + 1];
                    mma_f16(acc[mt][nt], a_r[mt], b0, b1);
                }
        }

        if (s + 1 < NST) {
#pragma unroll
            for (int u = 0; u < 8; ++u) {
                int idx = tid + u * 512;
                int row = idx >> 5, kq = (idx & 31) * 4;
                uint2 hv = make_uint2(cvt_h2(pf[u].x, pf[u].y), cvt_h2(pf[u].z, pf[u].w));
                *(uint2*)(sm + OFF_A(nb) + row * (ASTR * 2) + kq * 2) = hv;
            }
            CP_WAIT0();
        }
        __syncthreads();
    }

    // ---- epilogue: acc -> Fs (overlay), then per-column pooling ----
    {
        const int gid = lane >> 2, tig = lane & 3;
#pragma unroll
        for (int mt = 0; mt < 2; ++mt)
#pragma unroll
            for (int nt = 0; nt < 4; ++nt) {
                int m0 = wm * 32 + mt * 16 + gid;
                int n0 = wn * 32 + nt * 8 + tig * 2;
                Fs[m0 * EDIM + n0] = acc[mt][nt][0];
                Fs[m0 * EDIM + n0 + 1] = acc[mt][nt][1];
                Fs[(m0 + 8) * EDIM + n0] = acc[mt][nt][2];
                Fs[(m0 + 8) * EDIM + n0 + 1] = acc[mt][nt][3];
            }
    }
    __syncthreads();

    {
        const int sub = tid >> 7;       // 0..3, each handles 32 rows
        const int e = tid & 127;
        float t0 = -FLT_MAX, t1 = -FLT_MAX, t2 = -FLT_MAX;
        float m0 = FLT_MAX, m1 = FLT_MAX, m2 = FLT_MAX;
#pragma unroll 4
        for (int r = sub * 32; r < sub * 32 + 32; ++r) {
            float v = Fs[r * EDIM + e];
            ins_top(v, t0, t1, t2);
            ins_min(v, m0, m1, m2);
        }
        cand_s[sub][e][0] = t0; cand_s[sub][e][1] = t1; cand_s[sub][e][2] = t2;
        cand_s[sub][e][3] = m0; cand_s[sub][e][4] = m1; cand_s[sub][e][5] = m2;
    }
    __syncthreads();

    if (tid < EDIM) {
        float t0 = -FLT_MAX, t1 = -FLT_MAX, t2 = -FLT_MAX;
        float m0 = FLT_MAX, m1 = FLT_MAX, m2 = FLT_MAX;
#pragma unroll
        for (int s2 = 0; s2 < 4; ++s2) {
            ins_top(cand_s[s2][tid][0], t0, t1, t2);
            ins_top(cand_s[s2][tid][1], t0, t1, t2);
            ins_top(cand_s[s2][tid][2], t0, t1, t2);
            ins_min(cand_s[s2][tid][3], m0, m1, m2);
            ins_min(cand_s[s2][tid][4], m0, m1, m2);
            ins_min(cand_s[s2][tid][5], m0, m1, m2);
        }
        float* dst = g_cand + ((size_t)(b * NCHUNK + chunk) * EDIM + tid) * 6;
        dst[0] = t0; dst[1] = t1; dst[2] = t2;
        dst[3] = m0; dst[4] = m1; dst[5] = m2;
    }
}

// ================= kernel 2: merge + pool + L2 normalize =================
// grid = BATCH, block = (128, 8)
__global__ void weldon_reduce_kernel(float* __restrict__ out) {
    const int b = blockIdx.x;
    const int e = threadIdx.x;
    const int sub = threadIdx.y;

    __shared__ float cand_s[8][EDIM][6];
    __shared__ float ps_s[EDIM];
    __shared__ float wsum[4];

    float t0 = -FLT_MAX, t1 = -FLT_MAX, t2 = -FLT_MAX;
    float m0 = FLT_MAX, m1 = FLT_MAX, m2 = FLT_MAX;
    const float* bb = g_cand + (size_t)b * NCHUNK * EDIM * 6 + (size_t)e * 6;
#pragma unroll
    for (int c = sub; c < NCHUNK; c += 8) {
        const float* p = bb + (size_t)c * EDIM * 6;
        ins_top(p[0], t0, t1, t2);
        ins_top(p[1], t0, t1, t2);
        ins_top(p[2], t0, t1, t2);
        ins_min(p[3], m0, m1, m2);
        ins_min(p[4], m0, m1, m2);
        ins_min(p[5], m0, m1, m2);
    }
    cand_s[sub][e][0] = t0; cand_s[sub][e][1] = t1; cand_s[sub][e][2] = t2;
    cand_s[sub][e][3] = m0; cand_s[sub][e][4] = m1; cand_s[sub][e][5] = m2;
    __syncthreads();

    if (sub == 0) {
        for (int s2 = 1; s2 < 8; ++s2) {
            ins_top(cand_s[s2][e][0], t0, t1, t2);
            ins_top(cand_s[s2][e][1], t0, t1, t2);
            ins_top(cand_s[s2][e][2], t0, t1, t2);
            ins_min(cand_s[s2][e][3], m0, m1, m2);
            ins_min(cand_s[s2][e][4], m0, m1, m2);
            ins_min(cand_s[s2][e][5], m0, m1, m2);
        }
        float ps = (t0 + t1 + t2) + (m0 + m1 + m2);
        ps_s[e] = ps;
        float sq = ps * ps;
#pragma unroll
        for (int off = 16; off > 0; off >>= 1)
            sq += __shfl_xor_sync(0xffffffffu, sq, off);
        if ((e & 31) == 0) wsum[e >> 5] = sq;
    }
    __syncthreads();
    if (sub == 0) {
        float tot = wsum[0] + wsum[1] + wsum[2] + wsum[3];
        out[b * EDIM + e] = ps_s[e] * rsqrtf(fmaxf(tot, 1e-12f));
    }
}

extern "C" void kernel_launch(void* const* d_in, const int* in_sizes, int n_in,
                              void* d_out, int out_size) {
    const float* x = (const float*)d_in[0];   // [32, 64, 64, 512] fp32
    const float* W = (const float*)d_in[1];   // [512, 128] fp32
    float* out = (float*)d_out;               // [32, 128] fp32
    (void)in_sizes; (void)n_in; (void)out_size;

    cudaFuncSetAttribute(weldon_gemm_pool_kernel,
                         cudaFuncAttributeMaxDynamicSharedMemorySize, SMEM_DYN);

    weldon_prepw_kernel<<<64, 512>>>(W);
    weldon_gemm_pool_kernel<<<dim3(NCHUNK, BATCH), 512, SMEM_DYN>>>(x);
    weldon_reduce_kernel<<<BATCH, dim3(EDIM, 8)>>>(out);
}